// round 15
// baseline (speedup 1.0000x reference)
#include <cuda_runtime.h>
#include <cuda_fp16.h>
#include <mma.h>

#define NMAX 100000
#define EMAX 1600000

typedef unsigned long long ull;
using namespace nvcuda;

// ---------------- device scratch ----------------
__device__ int      g_cnt   [NMAX];
__device__ float    g_dinv  [NMAX];
__device__ __half   g_tmp16 [NMAX * 64];   // message buffer h*dinv (fp16)
__device__ __half   g_h16   [NMAX * 64];   // layer-1 output, BN/ReLU applied (fp16)
__device__ __half   g_h16b  [NMAX * 64];   // layer-2 output, +b2 applied (fp16)
__device__ float    g_logits[NMAX * 32];
__device__ float    g_wts   [NMAX];
__device__ int      g_rowptr[NMAX + 1];
__device__ int      g_epos  [EMAX];
__device__ int      g_csrc  [EMAX];
__device__ int      g_bsum  [64];
__device__ int      g_boff  [64];
__device__ unsigned g_tctr  [4];
__device__ unsigned g_done  = 0;
__device__ int      g_mmint [2];
__device__ float    g_acc   [33];

// ---------------- packed helpers ----------------
__device__ __forceinline__ ull pack2(float a, float b) {
    ull r; unsigned ia = __float_as_uint(a), ib = __float_as_uint(b);
    asm("mov.b64 %0, {%1, %2};" : "=l"(r) : "r"(ia), "r"(ib));
    return r;
}
__device__ __forceinline__ void ffma2(ull& d, ull a, ull b) {
    asm("fma.rn.f32x2 %0, %1, %2, %0;" : "+l"(d) : "l"(a), "l"(b));
}
__device__ __forceinline__ float2 unp(ull v) {
    float2 r; unsigned lo = (unsigned)v, hi = (unsigned)(v >> 32);
    r.x = __uint_as_float(lo); r.y = __uint_as_float(hi);
    return r;
}
__device__ __forceinline__ unsigned hadd2b(unsigned a, unsigned b) {
    unsigned r; asm("add.rn.f16x2 %0, %1, %2;" : "=r"(r) : "r"(a), "r"(b));
    return r;
}
__device__ __forceinline__ float4 h4_to_f4(uint2 h) {
    float2 lo = __half22float2(*(__half2*)&h.x);
    float2 hi = __half22float2(*(__half2*)&h.y);
    return make_float4(lo.x, lo.y, hi.x, hi.y);
}

// ---------------- degree count + arrival slot recording ----------------
__global__ void deg_count_k(const int* __restrict__ dstI, int e) {
    int i = (blockIdx.x * blockDim.x + threadIdx.x) * 4;
    if (i + 3 < e) {
        int d0 = __ldg(dstI + i);
        int d1 = __ldg(dstI + i + 1);
        int d2 = __ldg(dstI + i + 2);
        int d3 = __ldg(dstI + i + 3);
        int p0 = atomicAdd(&g_cnt[d0], 1);
        int p1 = atomicAdd(&g_cnt[d1], 1);
        int p2 = atomicAdd(&g_cnt[d2], 1);
        int p3 = atomicAdd(&g_cnt[d3], 1);
        *(int4*)(g_epos + i) = make_int4(p0, p1, p2, p3);
    } else {
        for (int k = 0; k < 4; k++)
            if (i + k < e)
                g_epos[i + k] = atomicAdd(&g_cnt[__ldg(dstI + i + k)], 1);
    }
}

// ---------------- CSR rowptr scan (last block does stage 2) ----------------
__global__ void __launch_bounds__(256) scan1_k(int n) {
    __shared__ int wsum[8];
    __shared__ bool sLast;
    int t = threadIdx.x;
    int base = blockIdx.x * 2048 + t * 8;
    int d[8]; int s = 0;
#pragma unroll
    for (int i = 0; i < 8; i++) {
        int idx = base + i;
        int c = (idx < n) ? g_cnt[idx] : 0;
        if (idx < n) g_dinv[idx] = rsqrtf((float)(c + 1));
        d[i] = c;
        s += c;
    }
    int lane = t & 31, w = t >> 5;
    int inc = s;
#pragma unroll
    for (int off = 1; off < 32; off <<= 1) {
        int v = __shfl_up_sync(0xffffffffu, inc, off);
        if (lane >= off) inc += v;
    }
    if (lane == 31) wsum[w] = inc;
    __syncthreads();
    if (w == 0) {
        int v = (lane < 8) ? wsum[lane] : 0;
#pragma unroll
        for (int off = 1; off < 8; off <<= 1) {
            int u = __shfl_up_sync(0xffffffffu, v, off);
            if (lane >= off) v += u;
        }
        if (lane < 8) wsum[lane] = v;
    }
    __syncthreads();
    int exc = inc - s + (w > 0 ? wsum[w - 1] : 0);
#pragma unroll
    for (int i = 0; i < 8; i++) {
        int idx = base + i;
        if (idx < n) g_rowptr[idx] = exc;
        exc += d[i];
    }
    if (t == 255) {
        g_bsum[blockIdx.x] = wsum[7];
        __threadfence();
        unsigned prev = atomicAdd(&g_done, 1u);
        sLast = (prev == gridDim.x - 1);
    }
    __syncthreads();
    if (sLast) {
        if (t == 0) g_done = 0;
        if (t < 32) {
            int nb = gridDim.x;
            int a = (lane      < nb) ? __ldcg(&g_bsum[lane])      : 0;
            int b = (lane + 32 < nb) ? __ldcg(&g_bsum[lane + 32]) : 0;
            int ia = a, ib = b;
#pragma unroll
            for (int off = 1; off < 32; off <<= 1) {
                int v = __shfl_up_sync(0xffffffffu, ia, off);
                if (lane >= off) ia += v;
                int u = __shfl_up_sync(0xffffffffu, ib, off);
                if (lane >= off) ib += u;
            }
            int sumA = __shfl_sync(0xffffffffu, ia, 31);
            g_boff[lane]      = ia - a;
            g_boff[lane + 32] = sumA + ib - b;
            if (lane == 0) {
                g_rowptr[n] = (n & 2047) ? __ldcg(&g_bsum[n >> 11]) : 0;
                g_mmint[0] = 0x7fffffff; g_mmint[1] = 0;
            }
            g_acc[lane] = 0.f;
            if (lane == 0) g_acc[32] = 0.f;
        }
    }
}

// ---------------- fill: atomic-free scatter ----------------
__global__ void fill_k(const int* __restrict__ srcI,
                       const int* __restrict__ dstI, int e) {
    int i = (blockIdx.x * blockDim.x + threadIdx.x) * 4;
    if (i + 3 < e) {
        int4 sv = *(const int4*)(srcI + i);
        int4 dv = *(const int4*)(dstI + i);
        int4 pv = *(const int4*)(g_epos + i);
        g_csrc[g_rowptr[dv.x] + g_boff[dv.x >> 11] + pv.x] = sv.x;
        g_csrc[g_rowptr[dv.y] + g_boff[dv.y >> 11] + pv.y] = sv.y;
        g_csrc[g_rowptr[dv.z] + g_boff[dv.z >> 11] + pv.z] = sv.z;
        g_csrc[g_rowptr[dv.w] + g_boff[dv.w >> 11] + pv.w] = sv.w;
    } else {
        for (int k = 0; k < 4; k++)
            if (i + k < e) {
                int d = __ldg(dstI + i + k);
                g_csrc[g_rowptr[d] + g_boff[d >> 11] + g_epos[i + k]] = __ldg(srcI + i + k);
            }
    }
}

// ---------------- scale: tmp16 *= dinv ----------------
__global__ void __launch_bounds__(256) scale_k(int n) {
    int i = blockIdx.x * blockDim.x + threadIdx.x;
    if (i >= n * 8) return;
    float dd = g_dinv[i >> 3];
    uint4 v = ((const uint4*)g_tmp16)[i];
    __half2* hp = (__half2*)&v;
#pragma unroll
    for (int j = 0; j < 4; j++) {
        float2 f = __half22float2(hp[j]);
        hp[j] = __floats2half2_rn(f.x * dd, f.y * dd);
    }
    ((uint4*)g_tmp16)[i] = v;
}

// ---------------- gemm0 (FFMA, fp32 input; hidden under CSR build) ----------------
__global__ void __launch_bounds__(256) gemm0_k(
    const float* __restrict__ Xin,
    const float* __restrict__ W,
    int n, int ntiles)
{
    __shared__ float4 Xs4[64 * 32];
    __shared__ float4 Ws4[64 * 16];
    __shared__ unsigned sh_tile;
    int t = threadIdx.x;
    const float4* W4 = (const float4*)W;
    for (int i = t; i < 1024; i += 256) Ws4[i] = W4[i];
    float* Xsf = (float*)Xs4;

    for (;;) {
        __syncthreads();
        if (t == 0) sh_tile = atomicAdd(&g_tctr[0], 1u);
        __syncthreads();
        int tile = (int)sh_tile;
        if (tile >= ntiles) break;
        int n0 = tile * 128;

        for (int i = t; i < 2048; i += 256) {
            int node = i >> 4, c4 = i & 15;
            int gn = n0 + node;
            float4 v = make_float4(0.f, 0.f, 0.f, 0.f);
            if (gn < n) v = ((const float4*)(Xin + (size_t)gn * 64))[c4];
            int g = node >> 2, lo = node & 3;
            int sg = g ^ (c4 & 7);
            float* base = Xsf + (c4 * 4) * 128 + sg * 4 + lo;
            base[0]   = v.x;
            base[128] = v.y;
            base[256] = v.z;
            base[384] = v.w;
        }
        __syncthreads();

        int ng = t & 31, og = t >> 5;
        ull acc2[4][4];
#pragma unroll
        for (int i = 0; i < 4; i++)
#pragma unroll
            for (int jp = 0; jp < 4; jp++) acc2[i][jp] = 0ull;
#pragma unroll 8
        for (int k = 0; k < 64; k++) {
            float4 xv = Xs4[k * 32 + (ng ^ ((k >> 2) & 7))];
            ulonglong2 wA = *(const ulonglong2*)&Ws4[k * 16 + og * 2];
            ulonglong2 wB = *(const ulonglong2*)&Ws4[k * 16 + og * 2 + 1];
            ull w2[4] = {wA.x, wA.y, wB.x, wB.y};
            float xa[4] = {xv.x, xv.y, xv.z, xv.w};
#pragma unroll
            for (int i = 0; i < 4; i++) {
                ull xd = pack2(xa[i], xa[i]);
#pragma unroll
                for (int jp = 0; jp < 4; jp++) ffma2(acc2[i][jp], xd, w2[jp]);
            }
        }
        int nb = n0 + 4 * ng;
#pragma unroll
        for (int i = 0; i < 4; i++) {
            int gn = nb + i;
            if (gn < n) {
                float2 p0 = unp(acc2[i][0]), p1 = unp(acc2[i][1]);
                float2 p2 = unp(acc2[i][2]), p3 = unp(acc2[i][3]);
                __half2 h0 = __floats2half2_rn(p0.x, p0.y);
                __half2 h1 = __floats2half2_rn(p1.x, p1.y);
                __half2 h2 = __floats2half2_rn(p2.x, p2.y);
                __half2 h3 = __floats2half2_rn(p3.x, p3.y);
                uint4 pk;
                pk.x = *(unsigned*)&h0; pk.y = *(unsigned*)&h1;
                pk.z = *(unsigned*)&h2; pk.w = *(unsigned*)&h3;
                *(uint4*)(g_tmp16 + (size_t)gn * 64 + og * 8) = pk;
            }
        }
    }
}

// ---------------- gemm1: WMMA fp16 tensor-core GEMM (h16 @ W2) -> tmp16 ----------------
// 128-node tiles, 8 warps; warp w owns nodes [16w,16w+16), all 64 outputs.
__global__ void __launch_bounds__(256) gemm1_wmma_k(
    const float* __restrict__ W,   // [64,64] fp32, converted to fp16 in smem
    int n, int ntiles)
{
    __shared__ __half Xh[128 * 72];     // 18 KB, stride 72 halves
    __shared__ __half Wh[64 * 64];      // 8 KB, row-major [k][j]
    __shared__ float  Scr[8 * 256];     // 8 KB per-warp epilogue scratch
    __shared__ unsigned sh_tile;
    int t = threadIdx.x;
    int w = t >> 5, lane = t & 31;

    for (int i = t; i < 4096; i += 256) Wh[i] = __float2half(W[i]);

    for (;;) {
        __syncthreads();
        if (t == 0) sh_tile = atomicAdd(&g_tctr[1], 1u);
        __syncthreads();
        int tile = (int)sh_tile;
        if (tile >= ntiles) break;
        int n0 = tile * 128;

        // load 128 x 64 halves (zero-fill OOB rows); 8 uint4 per row
        for (int i = t; i < 1024; i += 256) {
            int row = i >> 3, q = i & 7;
            int gn = n0 + row;
            uint4 v = make_uint4(0u, 0u, 0u, 0u);
            if (gn < n) v = ((const uint4*)g_h16)[(size_t)gn * 8 + q];
            *(uint4*)(Xh + row * 72 + q * 8) = v;
        }
        __syncthreads();

        wmma::fragment<wmma::accumulator, 16, 16, 16, float> acc[4];
#pragma unroll
        for (int jg = 0; jg < 4; jg++) wmma::fill_fragment(acc[jg], 0.0f);

#pragma unroll
        for (int kk = 0; kk < 4; kk++) {
            wmma::fragment<wmma::matrix_a, 16, 16, 16, __half, wmma::row_major> af;
            wmma::load_matrix_sync(af, Xh + (w * 16) * 72 + kk * 16, 72);
#pragma unroll
            for (int jg = 0; jg < 4; jg++) {
                wmma::fragment<wmma::matrix_b, 16, 16, 16, __half, wmma::row_major> bf;
                wmma::load_matrix_sync(bf, Wh + (kk * 16) * 64 + jg * 16, 64);
                wmma::mma_sync(acc[jg], af, bf, acc[jg]);
            }
        }

        // epilogue: per-warp scratch, scale by dinv, write fp16 tmp16
        float* sw = Scr + w * 256;
        int r  = lane >> 1;
        int c0 = (lane & 1) * 8;
        int gn = n0 + w * 16 + r;
        float dd = (gn < n) ? g_dinv[gn] : 0.f;
#pragma unroll
        for (int jg = 0; jg < 4; jg++) {
            wmma::store_matrix_sync(sw, acc[jg], 16, wmma::mem_row_major);
            if (gn < n) {
                const float* row = sw + r * 16 + c0;
                __half2 h0 = __floats2half2_rn(row[0] * dd, row[1] * dd);
                __half2 h1 = __floats2half2_rn(row[2] * dd, row[3] * dd);
                __half2 h2 = __floats2half2_rn(row[4] * dd, row[5] * dd);
                __half2 h3 = __floats2half2_rn(row[6] * dd, row[7] * dd);
                uint4 pk;
                pk.x = *(unsigned*)&h0; pk.y = *(unsigned*)&h1;
                pk.z = *(unsigned*)&h2; pk.w = *(unsigned*)&h3;
                *(uint4*)(g_tmp16 + (size_t)gn * 64 + jg * 16 + c0) = pk;
            }
            __syncwarp();
        }
    }
}

// ---------------- CSR gather: HADD2, fused epilogue, fp16 out ----------------
template<int WHICH>
__global__ void __launch_bounds__(256) gather_k(
    const float* __restrict__ p0,   // b1 | b2
    const float* __restrict__ p1,   // gamma | unused
    const float* __restrict__ p2,   // beta  | unused
    int n)
{
    int g = (blockIdx.x * blockDim.x + threadIdx.x) >> 4;
    int c = threadIdx.x & 15;
    if (g >= n) return;
    const uint2* T = (const uint2*)g_tmp16;
    uint2 self = T[(size_t)g * 16 + c];
    unsigned a0 = self.x, a1 = self.y;
    int j   = g_rowptr[g]     + g_boff[g >> 11];
    int end = g_rowptr[g + 1] + g_boff[(g + 1) >> 11];
    for (; j + 8 <= end; j += 8) {
        int s0 = __ldg(g_csrc + j);
        int s1 = __ldg(g_csrc + j + 1);
        int s2 = __ldg(g_csrc + j + 2);
        int s3 = __ldg(g_csrc + j + 3);
        int s4 = __ldg(g_csrc + j + 4);
        int s5 = __ldg(g_csrc + j + 5);
        int s6 = __ldg(g_csrc + j + 6);
        int s7 = __ldg(g_csrc + j + 7);
        uint2 v0 = T[(size_t)s0 * 16 + c];
        uint2 v1 = T[(size_t)s1 * 16 + c];
        uint2 v2 = T[(size_t)s2 * 16 + c];
        uint2 v3 = T[(size_t)s3 * 16 + c];
        uint2 v4 = T[(size_t)s4 * 16 + c];
        uint2 v5 = T[(size_t)s5 * 16 + c];
        uint2 v6 = T[(size_t)s6 * 16 + c];
        uint2 v7 = T[(size_t)s7 * 16 + c];
        a0 = hadd2b(a0, v0.x); a1 = hadd2b(a1, v0.y);
        a0 = hadd2b(a0, v1.x); a1 = hadd2b(a1, v1.y);
        a0 = hadd2b(a0, v2.x); a1 = hadd2b(a1, v2.y);
        a0 = hadd2b(a0, v3.x); a1 = hadd2b(a1, v3.y);
        a0 = hadd2b(a0, v4.x); a1 = hadd2b(a1, v4.y);
        a0 = hadd2b(a0, v5.x); a1 = hadd2b(a1, v5.y);
        a0 = hadd2b(a0, v6.x); a1 = hadd2b(a1, v6.y);
        a0 = hadd2b(a0, v7.x); a1 = hadd2b(a1, v7.y);
    }
    for (; j < end; j++) {
        int s0 = __ldg(g_csrc + j);
        uint2 v0 = T[(size_t)s0 * 16 + c];
        a0 = hadd2b(a0, v0.x); a1 = hadd2b(a1, v0.y);
    }
    float dd = g_dinv[g];
    float2 r0 = __half22float2(*(__half2*)&a0);
    float2 r1 = __half22float2(*(__half2*)&a1);
    float4 v = make_float4(r0.x * dd, r0.y * dd, r1.x * dd, r1.y * dd);

    if (WHICH == 0) {
        const float rs = rsqrtf(1.0f + 1e-5f);
        float4 bb = ((const float4*)p0)[c];
        float4 gm = ((const float4*)p1)[c];
        float4 bt = ((const float4*)p2)[c];
        v.x = fmaxf(fmaf(v.x + bb.x, rs * gm.x, bt.x), 0.f);
        v.y = fmaxf(fmaf(v.y + bb.y, rs * gm.y, bt.y), 0.f);
        v.z = fmaxf(fmaf(v.z + bb.z, rs * gm.z, bt.z), 0.f);
        v.w = fmaxf(fmaf(v.w + bb.w, rs * gm.w, bt.w), 0.f);
    } else {
        float4 bb = ((const float4*)p0)[c];
        v.x += bb.x; v.y += bb.y; v.z += bb.z; v.w += bb.w;
    }
    __half2 o0 = __floats2half2_rn(v.x, v.y);
    __half2 o1 = __floats2half2_rn(v.z, v.w);
    uint2 pk;
    pk.x = *(unsigned*)&o0; pk.y = *(unsigned*)&o1;
    __half* outp = (WHICH == 0) ? g_h16 : g_h16b;
    ((uint2*)outp)[(size_t)g * 16 + c] = pk;
}

// ---------------- persistent logits (fp16 input) + softmax/entropy + min/max ----------
__global__ void __launch_bounds__(128) logits_k(
    const float* __restrict__ W,    // [64,32] row-major
    const float* __restrict__ bb,   // [32]
    int n, int ntiles)
{
    __shared__ float4 Xs4[64 * 32];
    __shared__ float4 Wl4[64 * 8];
    __shared__ int smm[8];
    __shared__ unsigned sh_tile;
    int t = threadIdx.x;

    for (int i = t; i < 512; i += 128) Wl4[i] = ((const float4*)W)[i];
    float* Xsf = (float*)Xs4;

    for (;;) {
        __syncthreads();
        if (t == 0) sh_tile = atomicAdd(&g_tctr[2], 1u);
        __syncthreads();
        int tile = (int)sh_tile;
        if (tile >= ntiles) break;
        int n0 = tile * 128;

        for (int i = t; i < 2048; i += 128) {
            int node = i >> 4, c4 = i & 15;
            int gn = n0 + node;
            float4 v = make_float4(0.f, 0.f, 0.f, 0.f);
            if (gn < n) {
                uint2 hv = ((const uint2*)g_h16b)[(size_t)gn * 16 + c4];
                v = h4_to_f4(hv);
            }
            int g = node >> 2, lo = node & 3;
            int sg = g ^ (c4 & 7);
            float* base = Xsf + (c4 * 4) * 128 + sg * 4 + lo;
            base[0]   = v.x;
            base[128] = v.y;
            base[256] = v.z;
            base[384] = v.w;
        }
        __syncthreads();

        int ng = t & 31;
        int og = t >> 5;
        ull acc2[4][4];
        float4 bb0 = ((const float4*)bb)[og * 2];
        float4 bb1 = ((const float4*)bb)[og * 2 + 1];
        float bj[8] = {bb0.x, bb0.y, bb0.z, bb0.w, bb1.x, bb1.y, bb1.z, bb1.w};
#pragma unroll
        for (int i = 0; i < 4; i++)
#pragma unroll
            for (int jp = 0; jp < 4; jp++) acc2[i][jp] = pack2(bj[2 * jp], bj[2 * jp + 1]);

#pragma unroll 8
        for (int k = 0; k < 64; k++) {
            float4 xv = Xs4[k * 32 + (ng ^ ((k >> 2) & 7))];
            ulonglong2 wA = *(const ulonglong2*)&Wl4[k * 8 + og * 2];
            ulonglong2 wB = *(const ulonglong2*)&Wl4[k * 8 + og * 2 + 1];
            ull w2[4] = {wA.x, wA.y, wB.x, wB.y};
            float xa[4] = {xv.x, xv.y, xv.z, xv.w};
#pragma unroll
            for (int i = 0; i < 4; i++) {
                ull xd = pack2(xa[i], xa[i]);
#pragma unroll
                for (int jp = 0; jp < 4; jp++) ffma2(acc2[i][jp], xd, w2[jp]);
            }
        }
        __syncthreads();

        float* Ls = Xsf;
#pragma unroll
        for (int i = 0; i < 4; i++) {
            float2 p0 = unp(acc2[i][0]), p1 = unp(acc2[i][1]);
            float2 p2 = unp(acc2[i][2]), p3 = unp(acc2[i][3]);
            float* row = Ls + (4 * ng + i) * 33 + og * 8;
            row[0] = p0.x; row[1] = p0.y; row[2] = p1.x; row[3] = p1.y;
            row[4] = p2.x; row[5] = p2.y; row[6] = p3.x; row[7] = p3.y;
        }
        __syncthreads();

        int lane = t & 31;
        float wmn = 3.4e38f, wmx = 0.0f;
        for (int r = og; r < 128; r += 4) {
            int gn = n0 + r;
            float l = Ls[r * 33 + lane];
            float m = l;
#pragma unroll
            for (int off = 16; off; off >>= 1)
                m = fmaxf(m, __shfl_xor_sync(0xffffffffu, m, off));
            float p = expf(l - m);
            float sum = p;
#pragma unroll
            for (int off = 16; off; off >>= 1)
                sum += __shfl_xor_sync(0xffffffffu, sum, off);
            p /= sum;
            float term = -p * logf(p + 1e-9f);
#pragma unroll
            for (int off = 16; off; off >>= 1)
                term += __shfl_xor_sync(0xffffffffu, term, off);
            if (gn < n) {
                float wv = 1.0f / (term + 1e-10f);
                g_logits[(size_t)gn * 32 + lane] = l;
                if (lane == 0) {
                    g_wts[gn] = wv;
                    wmn = fminf(wmn, wv);
                    wmx = fmaxf(wmx, wv);
                }
            }
        }
        if (lane == 0) {
            smm[og * 2]     = __float_as_int(wmn);
            smm[og * 2 + 1] = __float_as_int(wmx);
        }
        __syncthreads();
        if (t == 0) {
            int mn = smm[0], mx = smm[1];
#pragma unroll
            for (int i = 1; i < 4; i++) {
                mn = min(mn, smm[i * 2]);
                mx = max(mx, smm[i * 2 + 1]);
            }
            atomicMin(&g_mmint[0], mn);
            atomicMax(&g_mmint[1], mx);
        }
    }
}

// ---------------- weighted sum + fused final matvec (last block) ----------------
__global__ void wsum_k(int n, const float* __restrict__ w3,
                       const float* __restrict__ b3, float* __restrict__ out) {
    __shared__ float sacc[8][33];
    __shared__ bool sl;
    int t = threadIdx.x, w = t >> 5, lane = t & 31;
    float mn = __int_as_float(g_mmint[0]);
    float den = __int_as_float(g_mmint[1]) - mn;
    float inv = den > 0.0f ? 1.0f / den : 0.0f;
    float acc = 0.0f, se = 0.0f;
    int warpG = blockIdx.x * 8 + w;
    int nwarp = gridDim.x * 8;
    for (int i = warpG; i < n; i += nwarp) {
        float e = expf((g_wts[i] - mn) * inv);
        acc += e * g_logits[(size_t)i * 32 + lane];
        se  += e;
    }
    sacc[w][lane] = acc;
    if (lane == 0) sacc[w][32] = se;
    __syncthreads();
    if (w == 0) {
        float a = sacc[0][lane];
#pragma unroll
        for (int r = 1; r < 8; r++) a += sacc[r][lane];
        atomicAdd(&g_acc[lane], a);
        if (lane == 0) {
            float b = sacc[0][32];
#pragma unroll
            for (int r = 1; r < 8; r++) b += sacc[r][32];
            atomicAdd(&g_acc[32], b);
        }
        __threadfence();
    }
    __syncthreads();
    if (t == 0) {
        unsigned prev = atomicAdd(&g_tctr[3], 1u);
        sl = (prev == gridDim.x - 1);
    }
    __syncthreads();
    if (sl && t < 64) {
        float invS = 1.0f / __ldcg(&g_acc[32]);
        float a = b3[t];
#pragma unroll
        for (int o = 0; o < 32; o++)
            a += (__ldcg(&g_acc[o]) * invS) * w3[o * 64 + t];
        out[t] = a;
    }
}

// ---------------- launch ----------------
extern "C" void kernel_launch(void* const* d_in, const int* in_sizes, int n_in,
                              void* d_out, int out_size) {
    const float* x     = (const float*)d_in[0];
    const int*   ei    = (const int*)  d_in[1];
    const float* W1    = (const float*)d_in[2];
    const float* b1    = (const float*)d_in[3];
    const float* gamma = (const float*)d_in[4];
    const float* beta  = (const float*)d_in[5];
    const float* W2    = (const float*)d_in[6];
    const float* b2    = (const float*)d_in[7];
    const float* l2w   = (const float*)d_in[8];
    const float* l2b   = (const float*)d_in[9];
    const float* l3w   = (const float*)d_in[10];
    const float* l3b   = (const float*)d_in[11];
    float* out = (float*)d_out;

    int n = in_sizes[0] / 64;
    int e = in_sizes[1] / 2;
    const int* srcI = ei;
    const int* dstI = ei + e;

    int ntiles = (n + 127) / 128;
    int gtb    = (n * 16 + 255) / 256;
    int scb    = (n + 2047) / 2048;

    void *cntPtr = nullptr, *tctrPtr = nullptr;
    cudaGetSymbolAddress(&cntPtr, g_cnt);
    cudaGetSymbolAddress(&tctrPtr, g_tctr);

    cudaStream_t s2;
    cudaEvent_t evStart, evScan, evB;
    cudaStreamCreateWithFlags(&s2, cudaStreamNonBlocking);
    cudaEventCreateWithFlags(&evStart, cudaEventDisableTiming);
    cudaEventCreateWithFlags(&evScan, cudaEventDisableTiming);
    cudaEventCreateWithFlags(&evB, cudaEventDisableTiming);

    cudaMemsetAsync(cntPtr, 0, (size_t)n * sizeof(int), 0);
    cudaMemsetAsync(tctrPtr, 0, 4 * sizeof(unsigned), 0);

    // fork: layer-1 GEMM (unscaled output) runs on s2 under the CSR build
    cudaEventRecord(evStart, 0);
    cudaStreamWaitEvent(s2, evStart, 0);
    gemm0_k<<<444, 256, 0, s2>>>(x, W1, n, ntiles);

    // main: degree+slots -> scan (dinv, rowptr) -> atomic-free fill
    deg_count_k<<<(e + 1023) / 1024, 256>>>(dstI, e);
    scan1_k    <<<scb, 256>>>(n);
    cudaEventRecord(evScan, 0);
    fill_k     <<<(e + 1023) / 1024, 256>>>(srcI, dstI, e);

    // s2: after dinv ready, scale tmp16 (overlaps fill)
    cudaStreamWaitEvent(s2, evScan, 0);
    scale_k<<<(n * 8 + 255) / 256, 256, 0, s2>>>(n);
    cudaEventRecord(evB, s2);

    // join, then propagate layer 1 (gather + BN/ReLU fused -> fp16 h1)
    cudaStreamWaitEvent(0, evB, 0);
    gather_k<0><<<gtb, 256>>>(b1, gamma, beta, n);

    // layer 2 GEMM on tensor cores (fp16 x fp16 -> fp32, dinv fused)
    gemm1_wmma_k<<<444, 256>>>(W2, n, ntiles);
    gather_k<1> <<<gtb, 256>>>(b2, nullptr, nullptr, n);

    // readout (fp16 input; b2 already applied)
    logits_k<<<740, 128>>>(l2w, l2b, n, ntiles);
    wsum_k  <<<128, 256>>>(n, l3w, l3b, out);
}

// round 16
// speedup vs baseline: 1.0097x; 1.0097x over previous
#include <cuda_runtime.h>
#include <cuda_fp16.h>

#define NMAX 100000
#define EMAX 1600000

typedef unsigned long long ull;

// ---------------- device scratch ----------------
__device__ int      g_cnt   [NMAX];
__device__ float    g_dinv  [NMAX];
__device__ __half   g_tmp16 [NMAX * 64];   // message buffer h*dinv (fp16)
__device__ __half   g_h16   [NMAX * 64];   // layer-1 output, BN/ReLU applied (fp16)
__device__ __half   g_h16b  [NMAX * 64];   // layer-2 output, +b2 applied (fp16)
__device__ float    g_logits[NMAX * 32];
__device__ float    g_wts   [NMAX];
__device__ int      g_rowptr[NMAX + 1];    // BLOCK-LOCAL exclusive prefix (add g_boff[i>>11])
__device__ int      g_epos  [EMAX];        // per-edge arrival slot (from deg_count)
__device__ int      g_csrc  [EMAX];
__device__ int      g_bsum  [64];
__device__ int      g_boff  [64];
__device__ unsigned g_tctr  [4];
__device__ unsigned g_done  = 0;
__device__ int      g_mmint [2];
__device__ float    g_acc   [33];

// ---------------- packed helpers ----------------
__device__ __forceinline__ ull pack2(float a, float b) {
    ull r; unsigned ia = __float_as_uint(a), ib = __float_as_uint(b);
    asm("mov.b64 %0, {%1, %2};" : "=l"(r) : "r"(ia), "r"(ib));
    return r;
}
__device__ __forceinline__ void ffma2(ull& d, ull a, ull b) {
    asm("fma.rn.f32x2 %0, %1, %2, %0;" : "+l"(d) : "l"(a), "l"(b));
}
__device__ __forceinline__ float2 unp(ull v) {
    float2 r; unsigned lo = (unsigned)v, hi = (unsigned)(v >> 32);
    r.x = __uint_as_float(lo); r.y = __uint_as_float(hi);
    return r;
}
__device__ __forceinline__ unsigned hadd2b(unsigned a, unsigned b) {
    unsigned r; asm("add.rn.f16x2 %0, %1, %2;" : "=r"(r) : "r"(a), "r"(b));
    return r;
}
__device__ __forceinline__ float4 h4_to_f4(uint2 h) {
    float2 lo = __half22float2(*(__half2*)&h.x);
    float2 hi = __half22float2(*(__half2*)&h.y);
    return make_float4(lo.x, lo.y, hi.x, hi.y);
}

// ---------------- degree count + arrival slot recording (8 edges/thread) ----------------
__global__ void deg_count_k(const int* __restrict__ dstI, int e) {
    int i = (blockIdx.x * blockDim.x + threadIdx.x) * 8;
    if (i + 7 < e) {
        int4 dA = *(const int4*)(dstI + i);
        int4 dB = *(const int4*)(dstI + i + 4);
        int p0 = atomicAdd(&g_cnt[dA.x], 1);
        int p1 = atomicAdd(&g_cnt[dA.y], 1);
        int p2 = atomicAdd(&g_cnt[dA.z], 1);
        int p3 = atomicAdd(&g_cnt[dA.w], 1);
        int p4 = atomicAdd(&g_cnt[dB.x], 1);
        int p5 = atomicAdd(&g_cnt[dB.y], 1);
        int p6 = atomicAdd(&g_cnt[dB.z], 1);
        int p7 = atomicAdd(&g_cnt[dB.w], 1);
        *(int4*)(g_epos + i)     = make_int4(p0, p1, p2, p3);
        *(int4*)(g_epos + i + 4) = make_int4(p4, p5, p6, p7);
    } else {
        for (int k = 0; k < 8; k++)
            if (i + k < e)
                g_epos[i + k] = atomicAdd(&g_cnt[__ldg(dstI + i + k)], 1);
    }
}

// ---------------- CSR rowptr scan (last block does stage 2) ----------------
__global__ void __launch_bounds__(256) scan1_k(int n) {
    __shared__ int wsum[8];
    __shared__ bool sLast;
    int t = threadIdx.x;
    int base = blockIdx.x * 2048 + t * 8;
    int d[8]; int s = 0;
#pragma unroll
    for (int i = 0; i < 8; i++) {
        int idx = base + i;
        int c = (idx < n) ? g_cnt[idx] : 0;
        if (idx < n) g_dinv[idx] = rsqrtf((float)(c + 1));
        d[i] = c;
        s += c;
    }
    int lane = t & 31, w = t >> 5;
    int inc = s;
#pragma unroll
    for (int off = 1; off < 32; off <<= 1) {
        int v = __shfl_up_sync(0xffffffffu, inc, off);
        if (lane >= off) inc += v;
    }
    if (lane == 31) wsum[w] = inc;
    __syncthreads();
    if (w == 0) {
        int v = (lane < 8) ? wsum[lane] : 0;
#pragma unroll
        for (int off = 1; off < 8; off <<= 1) {
            int u = __shfl_up_sync(0xffffffffu, v, off);
            if (lane >= off) v += u;
        }
        if (lane < 8) wsum[lane] = v;
    }
    __syncthreads();
    int exc = inc - s + (w > 0 ? wsum[w - 1] : 0);
#pragma unroll
    for (int i = 0; i < 8; i++) {
        int idx = base + i;
        if (idx < n) g_rowptr[idx] = exc;
        exc += d[i];
    }
    if (t == 255) {
        g_bsum[blockIdx.x] = wsum[7];
        __threadfence();
        unsigned prev = atomicAdd(&g_done, 1u);
        sLast = (prev == gridDim.x - 1);
    }
    __syncthreads();
    if (sLast) {
        if (t == 0) g_done = 0;
        if (t < 32) {
            int nb = gridDim.x;
            int a = (lane      < nb) ? __ldcg(&g_bsum[lane])      : 0;
            int b = (lane + 32 < nb) ? __ldcg(&g_bsum[lane + 32]) : 0;
            int ia = a, ib = b;
#pragma unroll
            for (int off = 1; off < 32; off <<= 1) {
                int v = __shfl_up_sync(0xffffffffu, ia, off);
                if (lane >= off) ia += v;
                int u = __shfl_up_sync(0xffffffffu, ib, off);
                if (lane >= off) ib += u;
            }
            int sumA = __shfl_sync(0xffffffffu, ia, 31);
            g_boff[lane]      = ia - a;
            g_boff[lane + 32] = sumA + ib - b;
            if (lane == 0) {
                g_rowptr[n] = (n & 2047) ? __ldcg(&g_bsum[n >> 11]) : 0;
                g_mmint[0] = 0x7fffffff; g_mmint[1] = 0;
            }
            g_acc[lane] = 0.f;
            if (lane == 0) g_acc[32] = 0.f;
        }
    }
}

// ---------------- fill: atomic-free scatter (8 edges/thread) ----------------
__global__ void fill_k(const int* __restrict__ srcI,
                       const int* __restrict__ dstI, int e) {
    int i = (blockIdx.x * blockDim.x + threadIdx.x) * 8;
    if (i + 7 < e) {
        int4 sA = *(const int4*)(srcI + i);
        int4 sB = *(const int4*)(srcI + i + 4);
        int4 dA = *(const int4*)(dstI + i);
        int4 dB = *(const int4*)(dstI + i + 4);
        int4 pA = *(const int4*)(g_epos + i);
        int4 pB = *(const int4*)(g_epos + i + 4);
        g_csrc[g_rowptr[dA.x] + g_boff[dA.x >> 11] + pA.x] = sA.x;
        g_csrc[g_rowptr[dA.y] + g_boff[dA.y >> 11] + pA.y] = sA.y;
        g_csrc[g_rowptr[dA.z] + g_boff[dA.z >> 11] + pA.z] = sA.z;
        g_csrc[g_rowptr[dA.w] + g_boff[dA.w >> 11] + pA.w] = sA.w;
        g_csrc[g_rowptr[dB.x] + g_boff[dB.x >> 11] + pB.x] = sB.x;
        g_csrc[g_rowptr[dB.y] + g_boff[dB.y >> 11] + pB.y] = sB.y;
        g_csrc[g_rowptr[dB.z] + g_boff[dB.z >> 11] + pB.z] = sB.z;
        g_csrc[g_rowptr[dB.w] + g_boff[dB.w >> 11] + pB.w] = sB.w;
    } else {
        for (int k = 0; k < 8; k++)
            if (i + k < e) {
                int d = __ldg(dstI + i + k);
                g_csrc[g_rowptr[d] + g_boff[d >> 11] + g_epos[i + k]] = __ldg(srcI + i + k);
            }
    }
}

// ---------------- scale: tmp16 *= dinv ----------------
__global__ void __launch_bounds__(256) scale_k(int n) {
    int i = blockIdx.x * blockDim.x + threadIdx.x;
    if (i >= n * 8) return;
    float dd = g_dinv[i >> 3];
    uint4 v = ((const uint4*)g_tmp16)[i];
    __half2* hp = (__half2*)&v;
#pragma unroll
    for (int j = 0; j < 4; j++) {
        float2 f = __half22float2(hp[j]);
        hp[j] = __floats2half2_rn(f.x * dd, f.y * dd);
    }
    ((uint4*)g_tmp16)[i] = v;
}

// ---------------- persistent fused GEMM: dynamic 128-node tiles ----------------
// MODE 0: X = Xin (fp32), writes UNSCALED h -> tmp16 (scale_k applies dinv).
// MODE 1: X = g_h16 (fp16), writes h*dinv -> tmp16.
template<int MODE>
__global__ void __launch_bounds__(256) gemm_fused_k(
    const float* __restrict__ Xin,
    const float* __restrict__ W,
    int n, int ntiles)
{
    __shared__ float4 Xs4[64 * 32];
    __shared__ float4 Ws4[64 * 16];
    __shared__ unsigned sh_tile;
    int t = threadIdx.x;

    const float4* W4 = (const float4*)W;
    for (int i = t; i < 1024; i += 256) Ws4[i] = W4[i];

    float* Xsf = (float*)Xs4;

    for (;;) {
        __syncthreads();
        if (t == 0) sh_tile = atomicAdd(&g_tctr[MODE], 1u);
        __syncthreads();
        int tile = (int)sh_tile;
        if (tile >= ntiles) break;
        int n0 = tile * 128;

        for (int i = t; i < 2048; i += 256) {
            int node = i >> 4, c4 = i & 15;
            int gn = n0 + node;
            float4 v = make_float4(0.f, 0.f, 0.f, 0.f);
            if (gn < n) {
                if (MODE == 0) {
                    v = ((const float4*)(Xin + (size_t)gn * 64))[c4];
                } else {
                    uint2 hv = ((const uint2*)g_h16)[(size_t)gn * 16 + c4];
                    v = h4_to_f4(hv);
                }
            }
            int g = node >> 2, lo = node & 3;
            int sg = g ^ (c4 & 7);
            float* base = Xsf + (c4 * 4) * 128 + sg * 4 + lo;
            base[0]   = v.x;
            base[128] = v.y;
            base[256] = v.z;
            base[384] = v.w;
        }
        __syncthreads();

        int ng = t & 31;
        int og = t >> 5;
        ull acc2[4][4];
#pragma unroll
        for (int i = 0; i < 4; i++)
#pragma unroll
            for (int jp = 0; jp < 4; jp++) acc2[i][jp] = 0ull;

#pragma unroll 8
        for (int k = 0; k < 64; k++) {
            float4 xv = Xs4[k * 32 + (ng ^ ((k >> 2) & 7))];
            ulonglong2 wA = *(const ulonglong2*)&Ws4[k * 16 + og * 2];
            ulonglong2 wB = *(const ulonglong2*)&Ws4[k * 16 + og * 2 + 1];
            ull w2[4] = {wA.x, wA.y, wB.x, wB.y};
            float xa[4] = {xv.x, xv.y, xv.z, xv.w};
#pragma unroll
            for (int i = 0; i < 4; i++) {
                ull xd = pack2(xa[i], xa[i]);
#pragma unroll
                for (int jp = 0; jp < 4; jp++) ffma2(acc2[i][jp], xd, w2[jp]);
            }
        }

        int nb = n0 + 4 * ng;
        if (nb < n) {
            float di[4] = {1.f, 1.f, 1.f, 1.f};
            if (MODE == 1) {
                float4 dv = *(const float4*)(g_dinv + nb);
                di[0] = dv.x; di[1] = dv.y; di[2] = dv.z; di[3] = dv.w;
            }
#pragma unroll
            for (int i = 0; i < 4; i++) {
                int gn = nb + i;
                if (gn < n) {
                    float2 p0 = unp(acc2[i][0]), p1 = unp(acc2[i][1]);
                    float2 p2 = unp(acc2[i][2]), p3 = unp(acc2[i][3]);
                    float s = di[i];
                    __half2 h0 = __floats2half2_rn(p0.x * s, p0.y * s);
                    __half2 h1 = __floats2half2_rn(p1.x * s, p1.y * s);
                    __half2 h2 = __floats2half2_rn(p2.x * s, p2.y * s);
                    __half2 h3 = __floats2half2_rn(p3.x * s, p3.y * s);
                    uint4 pk;
                    pk.x = *(unsigned*)&h0; pk.y = *(unsigned*)&h1;
                    pk.z = *(unsigned*)&h2; pk.w = *(unsigned*)&h3;
                    *(uint4*)(g_tmp16 + (size_t)gn * 64 + og * 8) = pk;
                }
            }
        }
    }
}

// ---------------- CSR gather: HADD2, fused epilogue, fp16 out ----------------
// WHICH 0: out = relu( (sum*dd + b1) * rs*gamma + beta )  -> g_h16
// WHICH 1: out = sum*dd + b2                              -> g_h16b
template<int WHICH>
__global__ void __launch_bounds__(256) gather_k(
    const float* __restrict__ p0,   // b1 | b2
    const float* __restrict__ p1,   // gamma | unused
    const float* __restrict__ p2,   // beta  | unused
    int n)
{
    int g = (blockIdx.x * blockDim.x + threadIdx.x) >> 4;
    int c = threadIdx.x & 15;
    if (g >= n) return;
    const uint2* T = (const uint2*)g_tmp16;
    uint2 self = T[(size_t)g * 16 + c];
    unsigned a0 = self.x, a1 = self.y;
    int j   = g_rowptr[g]     + g_boff[g >> 11];
    int end = g_rowptr[g + 1] + g_boff[(g + 1) >> 11];
    for (; j + 8 <= end; j += 8) {
        int s0 = __ldg(g_csrc + j);
        int s1 = __ldg(g_csrc + j + 1);
        int s2 = __ldg(g_csrc + j + 2);
        int s3 = __ldg(g_csrc + j + 3);
        int s4 = __ldg(g_csrc + j + 4);
        int s5 = __ldg(g_csrc + j + 5);
        int s6 = __ldg(g_csrc + j + 6);
        int s7 = __ldg(g_csrc + j + 7);
        uint2 v0 = T[(size_t)s0 * 16 + c];
        uint2 v1 = T[(size_t)s1 * 16 + c];
        uint2 v2 = T[(size_t)s2 * 16 + c];
        uint2 v3 = T[(size_t)s3 * 16 + c];
        uint2 v4 = T[(size_t)s4 * 16 + c];
        uint2 v5 = T[(size_t)s5 * 16 + c];
        uint2 v6 = T[(size_t)s6 * 16 + c];
        uint2 v7 = T[(size_t)s7 * 16 + c];
        a0 = hadd2b(a0, v0.x); a1 = hadd2b(a1, v0.y);
        a0 = hadd2b(a0, v1.x); a1 = hadd2b(a1, v1.y);
        a0 = hadd2b(a0, v2.x); a1 = hadd2b(a1, v2.y);
        a0 = hadd2b(a0, v3.x); a1 = hadd2b(a1, v3.y);
        a0 = hadd2b(a0, v4.x); a1 = hadd2b(a1, v4.y);
        a0 = hadd2b(a0, v5.x); a1 = hadd2b(a1, v5.y);
        a0 = hadd2b(a0, v6.x); a1 = hadd2b(a1, v6.y);
        a0 = hadd2b(a0, v7.x); a1 = hadd2b(a1, v7.y);
    }
    for (; j < end; j++) {
        int s0 = __ldg(g_csrc + j);
        uint2 v0 = T[(size_t)s0 * 16 + c];
        a0 = hadd2b(a0, v0.x); a1 = hadd2b(a1, v0.y);
    }
    float dd = g_dinv[g];
    float2 r0 = __half22float2(*(__half2*)&a0);
    float2 r1 = __half22float2(*(__half2*)&a1);
    float4 v = make_float4(r0.x * dd, r0.y * dd, r1.x * dd, r1.y * dd);

    if (WHICH == 0) {
        const float rs = rsqrtf(1.0f + 1e-5f);
        float4 bb = ((const float4*)p0)[c];
        float4 gm = ((const float4*)p1)[c];
        float4 bt = ((const float4*)p2)[c];
        v.x = fmaxf(fmaf(v.x + bb.x, rs * gm.x, bt.x), 0.f);
        v.y = fmaxf(fmaf(v.y + bb.y, rs * gm.y, bt.y), 0.f);
        v.z = fmaxf(fmaf(v.z + bb.z, rs * gm.z, bt.z), 0.f);
        v.w = fmaxf(fmaf(v.w + bb.w, rs * gm.w, bt.w), 0.f);
    } else {
        float4 bb = ((const float4*)p0)[c];
        v.x += bb.x; v.y += bb.y; v.z += bb.z; v.w += bb.w;
    }
    __half2 o0 = __floats2half2_rn(v.x, v.y);
    __half2 o1 = __floats2half2_rn(v.z, v.w);
    uint2 pk;
    pk.x = *(unsigned*)&o0; pk.y = *(unsigned*)&o1;
    __half* outp = (WHICH == 0) ? g_h16 : g_h16b;
    ((uint2*)outp)[(size_t)g * 16 + c] = pk;
}

// ---------------- persistent logits (fp16 input) + softmax/entropy + min/max ----------
__global__ void __launch_bounds__(128) logits_k(
    const float* __restrict__ W,    // [64,32] row-major
    const float* __restrict__ bb,   // [32]
    int n, int ntiles)
{
    __shared__ float4 Xs4[64 * 32];
    __shared__ float4 Wl4[64 * 8];
    __shared__ int smm[8];
    __shared__ unsigned sh_tile;
    int t = threadIdx.x;

    for (int i = t; i < 512; i += 128) Wl4[i] = ((const float4*)W)[i];
    float* Xsf = (float*)Xs4;

    for (;;) {
        __syncthreads();
        if (t == 0) sh_tile = atomicAdd(&g_tctr[2], 1u);
        __syncthreads();
        int tile = (int)sh_tile;
        if (tile >= ntiles) break;
        int n0 = tile * 128;

        for (int i = t; i < 2048; i += 128) {
            int node = i >> 4, c4 = i & 15;
            int gn = n0 + node;
            float4 v = make_float4(0.f, 0.f, 0.f, 0.f);
            if (gn < n) {
                uint2 hv = ((const uint2*)g_h16b)[(size_t)gn * 16 + c4];
                v = h4_to_f4(hv);
            }
            int g = node >> 2, lo = node & 3;
            int sg = g ^ (c4 & 7);
            float* base = Xsf + (c4 * 4) * 128 + sg * 4 + lo;
            base[0]   = v.x;
            base[128] = v.y;
            base[256] = v.z;
            base[384] = v.w;
        }
        __syncthreads();

        int ng = t & 31;
        int og = t >> 5;
        ull acc2[4][4];
        float4 bb0 = ((const float4*)bb)[og * 2];
        float4 bb1 = ((const float4*)bb)[og * 2 + 1];
        float bj[8] = {bb0.x, bb0.y, bb0.z, bb0.w, bb1.x, bb1.y, bb1.z, bb1.w};
#pragma unroll
        for (int i = 0; i < 4; i++)
#pragma unroll
            for (int jp = 0; jp < 4; jp++) acc2[i][jp] = pack2(bj[2 * jp], bj[2 * jp + 1]);

#pragma unroll 8
        for (int k = 0; k < 64; k++) {
            float4 xv = Xs4[k * 32 + (ng ^ ((k >> 2) & 7))];
            ulonglong2 wA = *(const ulonglong2*)&Wl4[k * 8 + og * 2];
            ulonglong2 wB = *(const ulonglong2*)&Wl4[k * 8 + og * 2 + 1];
            ull w2[4] = {wA.x, wA.y, wB.x, wB.y};
            float xa[4] = {xv.x, xv.y, xv.z, xv.w};
#pragma unroll
            for (int i = 0; i < 4; i++) {
                ull xd = pack2(xa[i], xa[i]);
#pragma unroll
                for (int jp = 0; jp < 4; jp++) ffma2(acc2[i][jp], xd, w2[jp]);
            }
        }
        __syncthreads();

        float* Ls = Xsf;
#pragma unroll
        for (int i = 0; i < 4; i++) {
            float2 p0 = unp(acc2[i][0]), p1 = unp(acc2[i][1]);
            float2 p2 = unp(acc2[i][2]), p3 = unp(acc2[i][3]);
            float* row = Ls + (4 * ng + i) * 33 + og * 8;
            row[0] = p0.x; row[1] = p0.y; row[2] = p1.x; row[3] = p1.y;
            row[4] = p2.x; row[5] = p2.y; row[6] = p3.x; row[7] = p3.y;
        }
        __syncthreads();

        int lane = t & 31;
        float wmn = 3.4e38f, wmx = 0.0f;
        for (int r = og; r < 128; r += 4) {
            int gn = n0 + r;
            float l = Ls[r * 33 + lane];
            float m = l;
#pragma unroll
            for (int off = 16; off; off >>= 1)
                m = fmaxf(m, __shfl_xor_sync(0xffffffffu, m, off));
            float p = expf(l - m);
            float sum = p;
#pragma unroll
            for (int off = 16; off; off >>= 1)
                sum += __shfl_xor_sync(0xffffffffu, sum, off);
            p /= sum;
            float term = -p * logf(p + 1e-9f);
#pragma unroll
            for (int off = 16; off; off >>= 1)
                term += __shfl_xor_sync(0xffffffffu, term, off);
            if (gn < n) {
                float wv = 1.0f / (term + 1e-10f);
                g_logits[(size_t)gn * 32 + lane] = l;
                if (lane == 0) {
                    g_wts[gn] = wv;
                    wmn = fminf(wmn, wv);
                    wmx = fmaxf(wmx, wv);
                }
            }
        }
        if (lane == 0) {
            smm[og * 2]     = __float_as_int(wmn);
            smm[og * 2 + 1] = __float_as_int(wmx);
        }
        __syncthreads();
        if (t == 0) {
            int mn = smm[0], mx = smm[1];
#pragma unroll
            for (int i = 1; i < 4; i++) {
                mn = min(mn, smm[i * 2]);
                mx = max(mx, smm[i * 2 + 1]);
            }
            atomicMin(&g_mmint[0], mn);
            atomicMax(&g_mmint[1], mx);
        }
    }
}

// ---------------- weighted sum + fused final matvec (last block) ----------------
__global__ void wsum_k(int n, const float* __restrict__ w3,
                       const float* __restrict__ b3, float* __restrict__ out) {
    __shared__ float sacc[8][33];
    __shared__ bool sl;
    int t = threadIdx.x, w = t >> 5, lane = t & 31;
    float mn = __int_as_float(g_mmint[0]);
    float den = __int_as_float(g_mmint[1]) - mn;
    float inv = den > 0.0f ? 1.0f / den : 0.0f;
    float acc = 0.0f, se = 0.0f;
    int warpG = blockIdx.x * 8 + w;
    int nwarp = gridDim.x * 8;
    for (int i = warpG; i < n; i += nwarp) {
        float e = expf((g_wts[i] - mn) * inv);
        acc += e * g_logits[(size_t)i * 32 + lane];
        se  += e;
    }
    sacc[w][lane] = acc;
    if (lane == 0) sacc[w][32] = se;
    __syncthreads();
    if (w == 0) {
        float a = sacc[0][lane];
#pragma unroll
        for (int r = 1; r < 8; r++) a += sacc[r][lane];
        atomicAdd(&g_acc[lane], a);
        if (lane == 0) {
            float b = sacc[0][32];
#pragma unroll
            for (int r = 1; r < 8; r++) b += sacc[r][32];
            atomicAdd(&g_acc[32], b);
        }
        __threadfence();
    }
    __syncthreads();
    if (t == 0) {
        unsigned prev = atomicAdd(&g_tctr[3], 1u);
        sl = (prev == gridDim.x - 1);
    }
    __syncthreads();
    if (sl && t < 64) {
        float invS = 1.0f / __ldcg(&g_acc[32]);
        float a = b3[t];
#pragma unroll
        for (int o = 0; o < 32; o++)
            a += (__ldcg(&g_acc[o]) * invS) * w3[o * 64 + t];
        out[t] = a;
    }
}

// ---------------- launch ----------------
extern "C" void kernel_launch(void* const* d_in, const int* in_sizes, int n_in,
                              void* d_out, int out_size) {
    const float* x     = (const float*)d_in[0];
    const int*   ei    = (const int*)  d_in[1];
    const float* W1    = (const float*)d_in[2];
    const float* b1    = (const float*)d_in[3];
    const float* gamma = (const float*)d_in[4];
    const float* beta  = (const float*)d_in[5];
    const float* W2    = (const float*)d_in[6];
    const float* b2    = (const float*)d_in[7];
    const float* l2w   = (const float*)d_in[8];
    const float* l2b   = (const float*)d_in[9];
    const float* l3w   = (const float*)d_in[10];
    const float* l3b   = (const float*)d_in[11];
    float* out = (float*)d_out;

    int n = in_sizes[0] / 64;
    int e = in_sizes[1] / 2;
    const int* srcI = ei;
    const int* dstI = ei + e;

    int ntiles = (n + 127) / 128;
    int gtb    = (n * 16 + 255) / 256;
    int scb    = (n + 2047) / 2048;

    void *cntPtr = nullptr, *tctrPtr = nullptr;
    cudaGetSymbolAddress(&cntPtr, g_cnt);
    cudaGetSymbolAddress(&tctrPtr, g_tctr);

    cudaStream_t s2;
    cudaEvent_t evStart, evScan, evB;
    cudaStreamCreateWithFlags(&s2, cudaStreamNonBlocking);
    cudaEventCreateWithFlags(&evStart, cudaEventDisableTiming);
    cudaEventCreateWithFlags(&evScan, cudaEventDisableTiming);
    cudaEventCreateWithFlags(&evB, cudaEventDisableTiming);

    cudaMemsetAsync(cntPtr, 0, (size_t)n * sizeof(int), 0);
    cudaMemsetAsync(tctrPtr, 0, 4 * sizeof(unsigned), 0);

    // fork: layer-1 GEMM (unscaled output) runs on s2 under the CSR build
    cudaEventRecord(evStart, 0);
    cudaStreamWaitEvent(s2, evStart, 0);
    gemm_fused_k<0><<<444, 256, 0, s2>>>(x, W1, n, ntiles);

    // main: degree+slots -> scan (dinv, rowptr) -> atomic-free fill
    deg_count_k<<<(e + 2047) / 2048, 256>>>(dstI, e);
    scan1_k    <<<scb, 256>>>(n);
    cudaEventRecord(evScan, 0);
    fill_k     <<<(e + 2047) / 2048, 256>>>(srcI, dstI, e);

    // s2: after dinv ready, scale tmp16 (overlaps fill)
    cudaStreamWaitEvent(s2, evScan, 0);
    scale_k<<<(n * 8 + 255) / 256, 256, 0, s2>>>(n);
    cudaEventRecord(evB, s2);

    // join, then propagate layer 1 (gather + BN/ReLU fused -> fp16 h1)
    cudaStreamWaitEvent(0, evB, 0);
    gather_k<0><<<gtb, 256>>>(b1, gamma, beta, n);

    // layer 2 (fp16 input; scaling fused in epilogue)
    gemm_fused_k<1><<<444, 256>>>(nullptr, W2, n, ntiles);
    gather_k<1>   <<<gtb, 256>>>(b2, nullptr, nullptr, n);

    // readout (fp16 input; b2 already applied)
    logits_k<<<740, 128>>>(l2w, l2b, n, ntiles);
    wsum_k  <<<128, 256>>>(n, l3w, l3b, out);
}

// round 17
// speedup vs baseline: 1.0677x; 1.0574x over previous
#include <cuda_runtime.h>
#include <cuda_fp16.h>

#define NMAX 100000
#define EMAX 1600000

typedef unsigned long long ull;

// ---------------- device scratch ----------------
__device__ int      g_cnt   [NMAX];
__device__ float    g_dinv  [NMAX];
__device__ __half   g_tmp16 [NMAX * 64];   // message buffer h*dinv (fp16)
__device__ __half   g_h16   [NMAX * 64];   // layer-1 output, BN/ReLU applied (fp16)
__device__ __half   g_h16b  [NMAX * 64];   // layer-2 output, +b2 applied (fp16)
__device__ float    g_logits[NMAX * 32];
__device__ float    g_wts   [NMAX];
__device__ int      g_rowptr[NMAX + 1];    // BLOCK-LOCAL exclusive prefix (add g_boff[i>>11])
__device__ int      g_epos  [EMAX];        // per-edge arrival slot (from deg_count)
__device__ int      g_csrc  [EMAX];
__device__ int      g_bsum  [64];
__device__ int      g_boff  [64];
__device__ unsigned g_tctr  [4];
__device__ unsigned g_done  = 0;
__device__ int      g_mmint [2];
__device__ float    g_acc   [33];

// ---------------- packed helpers ----------------
__device__ __forceinline__ ull pack2(float a, float b) {
    ull r; unsigned ia = __float_as_uint(a), ib = __float_as_uint(b);
    asm("mov.b64 %0, {%1, %2};" : "=l"(r) : "r"(ia), "r"(ib));
    return r;
}
__device__ __forceinline__ void ffma2(ull& d, ull a, ull b) {
    asm("fma.rn.f32x2 %0, %1, %2, %0;" : "+l"(d) : "l"(a), "l"(b));
}
__device__ __forceinline__ float2 unp(ull v) {
    float2 r; unsigned lo = (unsigned)v, hi = (unsigned)(v >> 32);
    r.x = __uint_as_float(lo); r.y = __uint_as_float(hi);
    return r;
}
__device__ __forceinline__ unsigned hadd2b(unsigned a, unsigned b) {
    unsigned r; asm("add.rn.f16x2 %0, %1, %2;" : "=r"(r) : "r"(a), "r"(b));
    return r;
}
__device__ __forceinline__ float4 h4_to_f4(uint2 h) {
    float2 lo = __half22float2(*(__half2*)&h.x);
    float2 hi = __half22float2(*(__half2*)&h.y);
    return make_float4(lo.x, lo.y, hi.x, hi.y);
}

// ---------------- degree count + arrival slot recording (4 edges/thread) ----------------
__global__ void deg_count_k(const int* __restrict__ dstI, int e) {
    int i = (blockIdx.x * blockDim.x + threadIdx.x) * 4;
    if (i + 3 < e) {
        int d0 = __ldg(dstI + i);
        int d1 = __ldg(dstI + i + 1);
        int d2 = __ldg(dstI + i + 2);
        int d3 = __ldg(dstI + i + 3);
        int p0 = atomicAdd(&g_cnt[d0], 1);
        int p1 = atomicAdd(&g_cnt[d1], 1);
        int p2 = atomicAdd(&g_cnt[d2], 1);
        int p3 = atomicAdd(&g_cnt[d3], 1);
        *(int4*)(g_epos + i) = make_int4(p0, p1, p2, p3);
    } else {
        for (int k = 0; k < 4; k++)
            if (i + k < e)
                g_epos[i + k] = atomicAdd(&g_cnt[__ldg(dstI + i + k)], 1);
    }
}

// ---------------- CSR rowptr scan (last block does stage 2) ----------------
__global__ void __launch_bounds__(256) scan1_k(int n) {
    __shared__ int wsum[8];
    __shared__ bool sLast;
    int t = threadIdx.x;
    int base = blockIdx.x * 2048 + t * 8;
    int d[8]; int s = 0;
#pragma unroll
    for (int i = 0; i < 8; i++) {
        int idx = base + i;
        int c = (idx < n) ? g_cnt[idx] : 0;
        if (idx < n) g_dinv[idx] = rsqrtf((float)(c + 1));
        d[i] = c;
        s += c;
    }
    int lane = t & 31, w = t >> 5;
    int inc = s;
#pragma unroll
    for (int off = 1; off < 32; off <<= 1) {
        int v = __shfl_up_sync(0xffffffffu, inc, off);
        if (lane >= off) inc += v;
    }
    if (lane == 31) wsum[w] = inc;
    __syncthreads();
    if (w == 0) {
        int v = (lane < 8) ? wsum[lane] : 0;
#pragma unroll
        for (int off = 1; off < 8; off <<= 1) {
            int u = __shfl_up_sync(0xffffffffu, v, off);
            if (lane >= off) v += u;
        }
        if (lane < 8) wsum[lane] = v;
    }
    __syncthreads();
    int exc = inc - s + (w > 0 ? wsum[w - 1] : 0);
#pragma unroll
    for (int i = 0; i < 8; i++) {
        int idx = base + i;
        if (idx < n) g_rowptr[idx] = exc;
        exc += d[i];
    }
    if (t == 255) {
        g_bsum[blockIdx.x] = wsum[7];
        __threadfence();
        unsigned prev = atomicAdd(&g_done, 1u);
        sLast = (prev == gridDim.x - 1);
    }
    __syncthreads();
    if (sLast) {
        if (t == 0) g_done = 0;
        if (t < 32) {
            int nb = gridDim.x;
            int a = (lane      < nb) ? __ldcg(&g_bsum[lane])      : 0;
            int b = (lane + 32 < nb) ? __ldcg(&g_bsum[lane + 32]) : 0;
            int ia = a, ib = b;
#pragma unroll
            for (int off = 1; off < 32; off <<= 1) {
                int v = __shfl_up_sync(0xffffffffu, ia, off);
                if (lane >= off) ia += v;
                int u = __shfl_up_sync(0xffffffffu, ib, off);
                if (lane >= off) ib += u;
            }
            int sumA = __shfl_sync(0xffffffffu, ia, 31);
            g_boff[lane]      = ia - a;
            g_boff[lane + 32] = sumA + ib - b;
            if (lane == 0) {
                g_rowptr[n] = (n & 2047) ? __ldcg(&g_bsum[n >> 11]) : 0;
                g_mmint[0] = 0x7fffffff; g_mmint[1] = 0;
            }
            g_acc[lane] = 0.f;
            if (lane == 0) g_acc[32] = 0.f;
        }
    }
}

// ---------------- fill: atomic-free scatter (4 edges/thread) ----------------
__global__ void fill_k(const int* __restrict__ srcI,
                       const int* __restrict__ dstI, int e) {
    int i = (blockIdx.x * blockDim.x + threadIdx.x) * 4;
    if (i + 3 < e) {
        int4 sv = *(const int4*)(srcI + i);
        int4 dv = *(const int4*)(dstI + i);
        int4 pv = *(const int4*)(g_epos + i);
        g_csrc[g_rowptr[dv.x] + g_boff[dv.x >> 11] + pv.x] = sv.x;
        g_csrc[g_rowptr[dv.y] + g_boff[dv.y >> 11] + pv.y] = sv.y;
        g_csrc[g_rowptr[dv.z] + g_boff[dv.z >> 11] + pv.z] = sv.z;
        g_csrc[g_rowptr[dv.w] + g_boff[dv.w >> 11] + pv.w] = sv.w;
    } else {
        for (int k = 0; k < 4; k++)
            if (i + k < e) {
                int d = __ldg(dstI + i + k);
                g_csrc[g_rowptr[d] + g_boff[d >> 11] + g_epos[i + k]] = __ldg(srcI + i + k);
            }
    }
}

// ---------------- scale: tmp16 *= dinv ----------------
__global__ void __launch_bounds__(256) scale_k(int n) {
    int i = blockIdx.x * blockDim.x + threadIdx.x;
    if (i >= n * 8) return;
    float dd = g_dinv[i >> 3];
    uint4 v = ((const uint4*)g_tmp16)[i];
    __half2* hp = (__half2*)&v;
#pragma unroll
    for (int j = 0; j < 4; j++) {
        float2 f = __half22float2(hp[j]);
        hp[j] = __floats2half2_rn(f.x * dd, f.y * dd);
    }
    ((uint4*)g_tmp16)[i] = v;
}

// ---------------- persistent fused GEMM: dynamic 128-node tiles ----------------
// MODE 0: X = Xin (fp32), writes UNSCALED h -> tmp16 (scale_k applies dinv).
// MODE 1: X = g_h16 (fp16), writes h*dinv -> tmp16.
template<int MODE>
__global__ void __launch_bounds__(256) gemm_fused_k(
    const float* __restrict__ Xin,
    const float* __restrict__ W,
    int n, int ntiles)
{
    __shared__ float4 Xs4[64 * 32];
    __shared__ float4 Ws4[64 * 16];
    __shared__ unsigned sh_tile;
    int t = threadIdx.x;

    const float4* W4 = (const float4*)W;
    for (int i = t; i < 1024; i += 256) Ws4[i] = W4[i];

    float* Xsf = (float*)Xs4;

    for (;;) {
        __syncthreads();
        if (t == 0) sh_tile = atomicAdd(&g_tctr[MODE], 1u);
        __syncthreads();
        int tile = (int)sh_tile;
        if (tile >= ntiles) break;
        int n0 = tile * 128;

        for (int i = t; i < 2048; i += 256) {
            int node = i >> 4, c4 = i & 15;
            int gn = n0 + node;
            float4 v = make_float4(0.f, 0.f, 0.f, 0.f);
            if (gn < n) {
                if (MODE == 0) {
                    v = ((const float4*)(Xin + (size_t)gn * 64))[c4];
                } else {
                    uint2 hv = ((const uint2*)g_h16)[(size_t)gn * 16 + c4];
                    v = h4_to_f4(hv);
                }
            }
            int g = node >> 2, lo = node & 3;
            int sg = g ^ (c4 & 7);
            float* base = Xsf + (c4 * 4) * 128 + sg * 4 + lo;
            base[0]   = v.x;
            base[128] = v.y;
            base[256] = v.z;
            base[384] = v.w;
        }
        __syncthreads();

        int ng = t & 31;
        int og = t >> 5;
        ull acc2[4][4];
#pragma unroll
        for (int i = 0; i < 4; i++)
#pragma unroll
            for (int jp = 0; jp < 4; jp++) acc2[i][jp] = 0ull;

#pragma unroll 8
        for (int k = 0; k < 64; k++) {
            float4 xv = Xs4[k * 32 + (ng ^ ((k >> 2) & 7))];
            ulonglong2 wA = *(const ulonglong2*)&Ws4[k * 16 + og * 2];
            ulonglong2 wB = *(const ulonglong2*)&Ws4[k * 16 + og * 2 + 1];
            ull w2[4] = {wA.x, wA.y, wB.x, wB.y};
            float xa[4] = {xv.x, xv.y, xv.z, xv.w};
#pragma unroll
            for (int i = 0; i < 4; i++) {
                ull xd = pack2(xa[i], xa[i]);
#pragma unroll
                for (int jp = 0; jp < 4; jp++) ffma2(acc2[i][jp], xd, w2[jp]);
            }
        }

        int nb = n0 + 4 * ng;
        if (nb < n) {
            float di[4] = {1.f, 1.f, 1.f, 1.f};
            if (MODE == 1) {
                float4 dv = *(const float4*)(g_dinv + nb);
                di[0] = dv.x; di[1] = dv.y; di[2] = dv.z; di[3] = dv.w;
            }
#pragma unroll
            for (int i = 0; i < 4; i++) {
                int gn = nb + i;
                if (gn < n) {
                    float2 p0 = unp(acc2[i][0]), p1 = unp(acc2[i][1]);
                    float2 p2 = unp(acc2[i][2]), p3 = unp(acc2[i][3]);
                    float s = di[i];
                    __half2 h0 = __floats2half2_rn(p0.x * s, p0.y * s);
                    __half2 h1 = __floats2half2_rn(p1.x * s, p1.y * s);
                    __half2 h2 = __floats2half2_rn(p2.x * s, p2.y * s);
                    __half2 h3 = __floats2half2_rn(p3.x * s, p3.y * s);
                    uint4 pk;
                    pk.x = *(unsigned*)&h0; pk.y = *(unsigned*)&h1;
                    pk.z = *(unsigned*)&h2; pk.w = *(unsigned*)&h3;
                    *(uint4*)(g_tmp16 + (size_t)gn * 64 + og * 8) = pk;
                }
            }
        }
    }
}

// ---------------- CSR gather: HADD2, fused epilogue, fp16 out ----------------
// WHICH 0: out = relu( (sum*dd + b1) * rs*gamma + beta )  -> g_h16
// WHICH 1: out = sum*dd + b2                              -> g_h16b
template<int WHICH>
__global__ void __launch_bounds__(256) gather_k(
    const float* __restrict__ p0,   // b1 | b2
    const float* __restrict__ p1,   // gamma | unused
    const float* __restrict__ p2,   // beta  | unused
    int n)
{
    int g = (blockIdx.x * blockDim.x + threadIdx.x) >> 4;
    int c = threadIdx.x & 15;
    if (g >= n) return;
    const uint2* T = (const uint2*)g_tmp16;
    uint2 self = T[(size_t)g * 16 + c];
    unsigned a0 = self.x, a1 = self.y;
    int j   = g_rowptr[g]     + g_boff[g >> 11];
    int end = g_rowptr[g + 1] + g_boff[(g + 1) >> 11];
    for (; j + 8 <= end; j += 8) {
        int s0 = __ldg(g_csrc + j);
        int s1 = __ldg(g_csrc + j + 1);
        int s2 = __ldg(g_csrc + j + 2);
        int s3 = __ldg(g_csrc + j + 3);
        int s4 = __ldg(g_csrc + j + 4);
        int s5 = __ldg(g_csrc + j + 5);
        int s6 = __ldg(g_csrc + j + 6);
        int s7 = __ldg(g_csrc + j + 7);
        uint2 v0 = T[(size_t)s0 * 16 + c];
        uint2 v1 = T[(size_t)s1 * 16 + c];
        uint2 v2 = T[(size_t)s2 * 16 + c];
        uint2 v3 = T[(size_t)s3 * 16 + c];
        uint2 v4 = T[(size_t)s4 * 16 + c];
        uint2 v5 = T[(size_t)s5 * 16 + c];
        uint2 v6 = T[(size_t)s6 * 16 + c];
        uint2 v7 = T[(size_t)s7 * 16 + c];
        a0 = hadd2b(a0, v0.x); a1 = hadd2b(a1, v0.y);
        a0 = hadd2b(a0, v1.x); a1 = hadd2b(a1, v1.y);
        a0 = hadd2b(a0, v2.x); a1 = hadd2b(a1, v2.y);
        a0 = hadd2b(a0, v3.x); a1 = hadd2b(a1, v3.y);
        a0 = hadd2b(a0, v4.x); a1 = hadd2b(a1, v4.y);
        a0 = hadd2b(a0, v5.x); a1 = hadd2b(a1, v5.y);
        a0 = hadd2b(a0, v6.x); a1 = hadd2b(a1, v6.y);
        a0 = hadd2b(a0, v7.x); a1 = hadd2b(a1, v7.y);
    }
    for (; j < end; j++) {
        int s0 = __ldg(g_csrc + j);
        uint2 v0 = T[(size_t)s0 * 16 + c];
        a0 = hadd2b(a0, v0.x); a1 = hadd2b(a1, v0.y);
    }
    float dd = g_dinv[g];
    float2 r0 = __half22float2(*(__half2*)&a0);
    float2 r1 = __half22float2(*(__half2*)&a1);
    float4 v = make_float4(r0.x * dd, r0.y * dd, r1.x * dd, r1.y * dd);

    if (WHICH == 0) {
        const float rs = rsqrtf(1.0f + 1e-5f);
        float4 bb = ((const float4*)p0)[c];
        float4 gm = ((const float4*)p1)[c];
        float4 bt = ((const float4*)p2)[c];
        v.x = fmaxf(fmaf(v.x + bb.x, rs * gm.x, bt.x), 0.f);
        v.y = fmaxf(fmaf(v.y + bb.y, rs * gm.y, bt.y), 0.f);
        v.z = fmaxf(fmaf(v.z + bb.z, rs * gm.z, bt.z), 0.f);
        v.w = fmaxf(fmaf(v.w + bb.w, rs * gm.w, bt.w), 0.f);
    } else {
        float4 bb = ((const float4*)p0)[c];
        v.x += bb.x; v.y += bb.y; v.z += bb.z; v.w += bb.w;
    }
    __half2 o0 = __floats2half2_rn(v.x, v.y);
    __half2 o1 = __floats2half2_rn(v.z, v.w);
    uint2 pk;
    pk.x = *(unsigned*)&o0; pk.y = *(unsigned*)&o1;
    __half* outp = (WHICH == 0) ? g_h16 : g_h16b;
    ((uint2*)outp)[(size_t)g * 16 + c] = pk;
}

// ---------------- persistent logits (fp16 input) + softmax/entropy + min/max ----------
__global__ void __launch_bounds__(128) logits_k(
    const float* __restrict__ W,    // [64,32] row-major
    const float* __restrict__ bb,   // [32]
    int n, int ntiles)
{
    __shared__ float4 Xs4[64 * 32];
    __shared__ float4 Wl4[64 * 8];
    __shared__ int smm[8];
    __shared__ unsigned sh_tile;
    int t = threadIdx.x;

    for (int i = t; i < 512; i += 128) Wl4[i] = ((const float4*)W)[i];
    float* Xsf = (float*)Xs4;

    for (;;) {
        __syncthreads();
        if (t == 0) sh_tile = atomicAdd(&g_tctr[2], 1u);
        __syncthreads();
        int tile = (int)sh_tile;
        if (tile >= ntiles) break;
        int n0 = tile * 128;

        for (int i = t; i < 2048; i += 128) {
            int node = i >> 4, c4 = i & 15;
            int gn = n0 + node;
            float4 v = make_float4(0.f, 0.f, 0.f, 0.f);
            if (gn < n) {
                uint2 hv = ((const uint2*)g_h16b)[(size_t)gn * 16 + c4];
                v = h4_to_f4(hv);
            }
            int g = node >> 2, lo = node & 3;
            int sg = g ^ (c4 & 7);
            float* base = Xsf + (c4 * 4) * 128 + sg * 4 + lo;
            base[0]   = v.x;
            base[128] = v.y;
            base[256] = v.z;
            base[384] = v.w;
        }
        __syncthreads();

        int ng = t & 31;
        int og = t >> 5;
        ull acc2[4][4];
        float4 bb0 = ((const float4*)bb)[og * 2];
        float4 bb1 = ((const float4*)bb)[og * 2 + 1];
        float bj[8] = {bb0.x, bb0.y, bb0.z, bb0.w, bb1.x, bb1.y, bb1.z, bb1.w};
#pragma unroll
        for (int i = 0; i < 4; i++)
#pragma unroll
            for (int jp = 0; jp < 4; jp++) acc2[i][jp] = pack2(bj[2 * jp], bj[2 * jp + 1]);

#pragma unroll 8
        for (int k = 0; k < 64; k++) {
            float4 xv = Xs4[k * 32 + (ng ^ ((k >> 2) & 7))];
            ulonglong2 wA = *(const ulonglong2*)&Wl4[k * 8 + og * 2];
            ulonglong2 wB = *(const ulonglong2*)&Wl4[k * 8 + og * 2 + 1];
            ull w2[4] = {wA.x, wA.y, wB.x, wB.y};
            float xa[4] = {xv.x, xv.y, xv.z, xv.w};
#pragma unroll
            for (int i = 0; i < 4; i++) {
                ull xd = pack2(xa[i], xa[i]);
#pragma unroll
                for (int jp = 0; jp < 4; jp++) ffma2(acc2[i][jp], xd, w2[jp]);
            }
        }
        __syncthreads();

        float* Ls = Xsf;
#pragma unroll
        for (int i = 0; i < 4; i++) {
            float2 p0 = unp(acc2[i][0]), p1 = unp(acc2[i][1]);
            float2 p2 = unp(acc2[i][2]), p3 = unp(acc2[i][3]);
            float* row = Ls + (4 * ng + i) * 33 + og * 8;
            row[0] = p0.x; row[1] = p0.y; row[2] = p1.x; row[3] = p1.y;
            row[4] = p2.x; row[5] = p2.y; row[6] = p3.x; row[7] = p3.y;
        }
        __syncthreads();

        int lane = t & 31;
        float wmn = 3.4e38f, wmx = 0.0f;
        for (int r = og; r < 128; r += 4) {
            int gn = n0 + r;
            float l = Ls[r * 33 + lane];
            float m = l;
#pragma unroll
            for (int off = 16; off; off >>= 1)
                m = fmaxf(m, __shfl_xor_sync(0xffffffffu, m, off));
            float p = expf(l - m);
            float sum = p;
#pragma unroll
            for (int off = 16; off; off >>= 1)
                sum += __shfl_xor_sync(0xffffffffu, sum, off);
            p /= sum;
            float term = -p * logf(p + 1e-9f);
#pragma unroll
            for (int off = 16; off; off >>= 1)
                term += __shfl_xor_sync(0xffffffffu, term, off);
            if (gn < n) {
                float wv = 1.0f / (term + 1e-10f);
                g_logits[(size_t)gn * 32 + lane] = l;
                if (lane == 0) {
                    g_wts[gn] = wv;
                    wmn = fminf(wmn, wv);
                    wmx = fmaxf(wmx, wv);
                }
            }
        }
        if (lane == 0) {
            smm[og * 2]     = __float_as_int(wmn);
            smm[og * 2 + 1] = __float_as_int(wmx);
        }
        __syncthreads();
        if (t == 0) {
            int mn = smm[0], mx = smm[1];
#pragma unroll
            for (int i = 1; i < 4; i++) {
                mn = min(mn, smm[i * 2]);
                mx = max(mx, smm[i * 2 + 1]);
            }
            atomicMin(&g_mmint[0], mn);
            atomicMax(&g_mmint[1], mx);
        }
    }
}

// ---------------- weighted sum + fused final matvec (last block) ----------------
__global__ void wsum_k(int n, const float* __restrict__ w3,
                       const float* __restrict__ b3, float* __restrict__ out) {
    __shared__ float sacc[8][33];
    __shared__ bool sl;
    int t = threadIdx.x, w = t >> 5, lane = t & 31;
    float mn = __int_as_float(g_mmint[0]);
    float den = __int_as_float(g_mmint[1]) - mn;
    float inv = den > 0.0f ? 1.0f / den : 0.0f;
    float acc = 0.0f, se = 0.0f;
    int warpG = blockIdx.x * 8 + w;
    int nwarp = gridDim.x * 8;
    for (int i = warpG; i < n; i += nwarp) {
        float e = expf((g_wts[i] - mn) * inv);
        acc += e * g_logits[(size_t)i * 32 + lane];
        se  += e;
    }
    sacc[w][lane] = acc;
    if (lane == 0) sacc[w][32] = se;
    __syncthreads();
    if (w == 0) {
        float a = sacc[0][lane];
#pragma unroll
        for (int r = 1; r < 8; r++) a += sacc[r][lane];
        atomicAdd(&g_acc[lane], a);
        if (lane == 0) {
            float b = sacc[0][32];
#pragma unroll
            for (int r = 1; r < 8; r++) b += sacc[r][32];
            atomicAdd(&g_acc[32], b);
        }
        __threadfence();
    }
    __syncthreads();
    if (t == 0) {
        unsigned prev = atomicAdd(&g_tctr[3], 1u);
        sl = (prev == gridDim.x - 1);
    }
    __syncthreads();
    if (sl && t < 64) {
        float invS = 1.0f / __ldcg(&g_acc[32]);
        float a = b3[t];
#pragma unroll
        for (int o = 0; o < 32; o++)
            a += (__ldcg(&g_acc[o]) * invS) * w3[o * 64 + t];
        out[t] = a;
    }
}

// ---------------- launch ----------------
extern "C" void kernel_launch(void* const* d_in, const int* in_sizes, int n_in,
                              void* d_out, int out_size) {
    const float* x     = (const float*)d_in[0];
    const int*   ei    = (const int*)  d_in[1];
    const float* W1    = (const float*)d_in[2];
    const float* b1    = (const float*)d_in[3];
    const float* gamma = (const float*)d_in[4];
    const float* beta  = (const float*)d_in[5];
    const float* W2    = (const float*)d_in[6];
    const float* b2    = (const float*)d_in[7];
    const float* l2w   = (const float*)d_in[8];
    const float* l2b   = (const float*)d_in[9];
    const float* l3w   = (const float*)d_in[10];
    const float* l3b   = (const float*)d_in[11];
    float* out = (float*)d_out;

    int n = in_sizes[0] / 64;
    int e = in_sizes[1] / 2;
    const int* srcI = ei;
    const int* dstI = ei + e;

    int ntiles = (n + 127) / 128;
    int gtb    = (n * 16 + 255) / 256;
    int scb    = (n + 2047) / 2048;

    void *cntPtr = nullptr, *tctrPtr = nullptr;
    cudaGetSymbolAddress(&cntPtr, g_cnt);
    cudaGetSymbolAddress(&tctrPtr, g_tctr);

    cudaStream_t s2;
    cudaEvent_t evStart, evScan, evB;
    cudaStreamCreateWithFlags(&s2, cudaStreamNonBlocking);
    cudaEventCreateWithFlags(&evStart, cudaEventDisableTiming);
    cudaEventCreateWithFlags(&evScan, cudaEventDisableTiming);
    cudaEventCreateWithFlags(&evB, cudaEventDisableTiming);

    cudaMemsetAsync(cntPtr, 0, (size_t)n * sizeof(int), 0);
    cudaMemsetAsync(tctrPtr, 0, 4 * sizeof(unsigned), 0);

    // fork: layer-1 GEMM (unscaled output) runs on s2 under the CSR build
    cudaEventRecord(evStart, 0);
    cudaStreamWaitEvent(s2, evStart, 0);
    gemm_fused_k<0><<<444, 256, 0, s2>>>(x, W1, n, ntiles);

    // main: degree+slots -> scan (dinv, rowptr) -> atomic-free fill
    deg_count_k<<<(e + 1023) / 1024, 256>>>(dstI, e);
    scan1_k    <<<scb, 256>>>(n);
    cudaEventRecord(evScan, 0);
    fill_k     <<<(e + 1023) / 1024, 256>>>(srcI, dstI, e);

    // s2: after dinv ready, scale tmp16 (overlaps fill)
    cudaStreamWaitEvent(s2, evScan, 0);
    scale_k<<<(n * 8 + 255) / 256, 256, 0, s2>>>(n);
    cudaEventRecord(evB, s2);

    // join, then propagate layer 1 (gather + BN/ReLU fused -> fp16 h1)
    cudaStreamWaitEvent(0, evB, 0);
    gather_k<0><<<gtb, 256>>>(b1, gamma, beta, n);

    // layer 2 (fp16 input; scaling fused in epilogue)
    gemm_fused_k<1><<<444, 256>>>(nullptr, W2, n, ntiles);
    gather_k<1>   <<<gtb, 256>>>(b2, nullptr, nullptr, n);

    // readout (fp16 input; b2 already applied)
    logits_k<<<745, 128>>>(l2w, l2b, n, ntiles);
    wsum_k  <<<296, 256>>>(n, l3w, l3b, out);
}